// round 3
// baseline (speedup 1.0000x reference)
#include <cuda_runtime.h>

#define N_ROWS 8000
#define D 9
#define N4 2000           // N_ROWS / 4
#define OUT_TPB 256
#define ROWS_PER_BLK 16
#define PRO_TPB 1024
#define RPT 8             // 1000 active threads * 8 rows = 8000

// Scratch (device globals — no allocation allowed)
__device__ float d_g[N_ROWS];
__device__ float d_h[N_ROWS];
__device__ float d_w1bar[N_ROWS];

// ---------------------------------------------------------------------------
// Fused prologue (single block, 1024 threads; threads 0..999 own rows
// [t*8, t*8+8) = 72 contiguous floats = 18 aligned float4 loads).
//
// Key identity: w1bar[r] = 1/(1+exp(S1[r]-S2[r])) and
//   S1-S2 = cumsum_r( sum_d [ ((x-c1)/a1)^2 - ((x-c2)/a2)^2 ] )
// -> only ONE scan surface (delta), kept in SMEM (32 KB) to avoid register
//    arrays / spills. FC weights live in SMEM too.
// ---------------------------------------------------------------------------
__global__ void __launch_bounds__(PRO_TPB)
k_prologue(const float* __restrict__ x,
           const float* __restrict__ a1, const float* __restrict__ c1,
           const float* __restrict__ a2, const float* __restrict__ c2,
           const float* __restrict__ wf1, const float* __restrict__ bf1,
           const float* __restrict__ wf2, const float* __restrict__ bf2)
{
    __shared__ float smd[N_ROWS];     // per-row delta (32 KB)
    __shared__ float sh[PRO_TPB];     // thread totals for the block scan
    __shared__ float sW1[12], sW2[12], sPar[8];

    const int t = threadIdx.x;

    if (t < D)       { sW1[t] = wf1[t]; sW2[t] = wf2[t]; }
    else if (t == 9)  sPar[0] = c1[0];
    else if (t == 10) sPar[1] = 1.0f / a1[0];
    else if (t == 11) sPar[2] = c2[0];
    else if (t == 12) sPar[3] = 1.0f / a2[0];
    else if (t == 13) sPar[4] = bf1[0];
    else if (t == 14) sPar[5] = bf2[0];
    __syncthreads();

    const float C1 = sPar[0], inv1 = sPar[1];
    const float C2 = sPar[2], inv2 = sPar[3];
    const float B1 = sPar[4], B2 = sPar[5];

    const bool active = (t * RPT) < N_ROWS;   // threads 0..999
    float acc = 0.0f;

    if (active) {
        const float4* px = reinterpret_cast<const float4*>(x) + t * 18;
#pragma unroll 1
        for (int jb = 0; jb < 2; jb++) {      // 2 groups of 4 rows (9 float4 each)
            float el[36];
#pragma unroll
            for (int q = 0; q < 9; q++) {
                float4 v = px[jb * 9 + q];
                el[q * 4 + 0] = v.x; el[q * 4 + 1] = v.y;
                el[q * 4 + 2] = v.z; el[q * 4 + 3] = v.w;
            }
#pragma unroll
            for (int rl = 0; rl < 4; rl++) {
                float s = 0.0f, f1 = B1, f2 = B2;
#pragma unroll
                for (int d = 0; d < D; d++) {
                    float xv = el[rl * D + d];
                    float u1 = (xv - C1) * inv1;
                    float u2 = (xv - C2) * inv2;
                    s += fmaf(u1, u1, -u2 * u2);
                    f1 = fmaf(xv, sW1[d], f1);
                    f2 = fmaf(xv, sW2[d], f2);
                }
                int r = t * RPT + jb * 4 + rl;
                acc += s;
                smd[r] = s;
                d_g[r] = f1 - f2;
                d_h[r] = f2;
            }
        }
    }
    sh[t] = acc;
    __syncthreads();

    // Hillis-Steele inclusive scan over the 1024 thread totals
    for (int ofs = 1; ofs < PRO_TPB; ofs <<= 1) {
        float v = (t >= ofs) ? sh[t - ofs] : 0.0f;
        __syncthreads();
        sh[t] += v;
        __syncthreads();
    }

    if (active) {
        float run = (t > 0) ? sh[t - 1] : 0.0f;   // exclusive offset
        float w[RPT];
#pragma unroll
        for (int k = 0; k < RPT; k++) {
            run += smd[t * RPT + k];              // S1[r] - S2[r]
            w[k] = 1.0f / (1.0f + __expf(run));   // w1/(w1+w2), stable
        }
        float4* pw = reinterpret_cast<float4*>(d_w1bar) + t * 2;
        pw[0] = make_float4(w[0], w[1], w[2], w[3]);
        pw[1] = make_float4(w[4], w[5], w[6], w[7]);
    }
}

// ---------------------------------------------------------------------------
// Kernel 2: out[i, j] = h[i] + g[i] * w1bar[j]   (256 MB of stores — the cost)
// At the write roofline (DRAM 65.5% in ncu); unchanged.
// ---------------------------------------------------------------------------
__global__ void k_outer(float* __restrict__ out)
{
    int j4 = blockIdx.x * OUT_TPB + threadIdx.x;
    if (j4 >= N4) return;

    float4 w4 = reinterpret_cast<const float4*>(d_w1bar)[j4];
    int i0 = blockIdx.y * ROWS_PER_BLK;
    float4* o4 = reinterpret_cast<float4*>(out);

#pragma unroll
    for (int k = 0; k < ROWS_PER_BLK; k++) {
        int i = i0 + k;
        float gv = d_g[i];
        float hv = d_h[i];
        float4 o;
        o.x = fmaf(gv, w4.x, hv);
        o.y = fmaf(gv, w4.y, hv);
        o.z = fmaf(gv, w4.z, hv);
        o.w = fmaf(gv, w4.w, hv);
        __stcs(&o4[(size_t)i * N4 + j4], o);
    }
}

// ---------------------------------------------------------------------------
extern "C" void kernel_launch(void* const* d_in, const int* in_sizes, int n_in,
                              void* d_out, int out_size)
{
    const float* x   = (const float*)d_in[0];
    const float* a1  = (const float*)d_in[1];
    const float* c1  = (const float*)d_in[2];
    const float* a2  = (const float*)d_in[3];
    const float* c2  = (const float*)d_in[4];
    const float* wf1 = (const float*)d_in[5];
    const float* bf1 = (const float*)d_in[6];
    const float* wf2 = (const float*)d_in[7];
    const float* bf2 = (const float*)d_in[8];
    float* out = (float*)d_out;

    k_prologue<<<1, PRO_TPB>>>(x, a1, c1, a2, c2, wf1, bf1, wf2, bf2);

    dim3 grid((N4 + OUT_TPB - 1) / OUT_TPB, N_ROWS / ROWS_PER_BLK);  // (8, 500)
    k_outer<<<grid, OUT_TPB>>>(out);
}

// round 4
// speedup vs baseline: 1.1429x; 1.1429x over previous
#include <cuda_runtime.h>

#define N_ROWS 8000
#define D 9
#define N4 2000            // N_ROWS / 4 (float4 columns)
#define TPB 256
#define ROWS_PER_BLK 16
#define GRID_X 8           // 8*256 = 2048 >= 2000 column-float4s
#define GRID_Y 500         // 500*16 = 8000 rows
#define TOTAL_BLOCKS (GRID_X * GRID_Y)
#define PRO_ACT 250        // active prologue threads
#define PRO_RPT 32         // rows per prologue thread (250*32 = 8000)

// Scratch (device globals — zero-initialized at load, no allocation allowed)
__device__ float d_g[N_ROWS];
__device__ float d_h[N_ROWS];
__device__ float d_w1bar[N_ROWS];
__device__ unsigned int d_flag;   // 0 -> prologue pending, 1 -> done
__device__ unsigned int d_fin;    // finished-block counter (self-reset)

// ---------------------------------------------------------------------------
// ONE kernel. Block (0,0) runs the prologue:
//   delta[r] = sum_d [ ((x-c1)/a1)^2 - ((x-c2)/a2)^2 ]
//   run[r]   = cumsum(delta)            ( = S1[r]-S2[r], log-domain cumprod )
//   w1bar[r] = 1/(1+exp(run[r]))        ( stable 2-rule softmax )
//   g[r] = f1[r]-f2[r],  h[r] = f2[r]
// then releases d_flag. All blocks then write their output tile:
//   out[i,j] = h[i] + g[i]*w1bar[j]     (256 MB of streaming stores = the cost)
// Last block to finish resets d_flag/d_fin so graph replays are identical.
// ---------------------------------------------------------------------------
__global__ void __launch_bounds__(TPB)
k_fused(const float* __restrict__ x,
        const float* __restrict__ a1, const float* __restrict__ c1,
        const float* __restrict__ a2, const float* __restrict__ c2,
        const float* __restrict__ wf1, const float* __restrict__ bf1,
        const float* __restrict__ wf2, const float* __restrict__ bf2,
        float* __restrict__ out)
{
    __shared__ float smd[N_ROWS];     // per-row delta (32 KB), leader block only
    __shared__ float swsum[8], swoff[8];
    __shared__ float sW1[D], sW2[D];

    const int t = threadIdx.x;
    const bool leader = (blockIdx.x == 0 && blockIdx.y == 0);

    if (leader) {
        // ---- prologue ----
        if (t < D) { sW1[t] = wf1[t]; sW2[t] = wf2[t]; }
        __syncthreads();

        const float inv1 = 1.0f / a1[0];
        const float inv2 = 1.0f / a2[0];
        const float k1 = -c1[0] * inv1;     // u1 = fmaf(xv, inv1, k1)
        const float k2 = -c2[0] * inv2;
        const float B1 = bf1[0], B2 = bf2[0];

        float acc = 0.0f;
        if (t < PRO_ACT) {
            const float4* px = reinterpret_cast<const float4*>(x) + t * 72;
            const int rbase = t * PRO_RPT;
#pragma unroll 1
            for (int blk = 0; blk < 8; blk++) {     // 8 groups of 4 rows (9 float4)
                float el[36];
#pragma unroll
                for (int q = 0; q < 9; q++) {
                    float4 v = px[blk * 9 + q];
                    el[q * 4 + 0] = v.x; el[q * 4 + 1] = v.y;
                    el[q * 4 + 2] = v.z; el[q * 4 + 3] = v.w;
                }
#pragma unroll
                for (int rl = 0; rl < 4; rl++) {
                    float s1 = 0.f, s2 = 0.f, f1 = B1, f2 = B2;
#pragma unroll
                    for (int d = 0; d < D; d++) {
                        float xv = el[rl * D + d];
                        float u1 = fmaf(xv, inv1, k1);
                        float u2 = fmaf(xv, inv2, k2);
                        s1 = fmaf(u1, u1, s1);
                        s2 = fmaf(u2, u2, s2);
                        f1 = fmaf(xv, sW1[d], f1);
                        f2 = fmaf(xv, sW2[d], f2);
                    }
                    const int r = rbase + blk * 4 + rl;
                    const float delta = s1 - s2;
                    acc += delta;
                    smd[r] = delta;
                    d_g[r] = f1 - f2;
                    d_h[r] = f2;
                }
            }
        }
        // block scan of per-thread totals (warp shfl + tiny serial warp prefix)
        const unsigned lane = t & 31, wid = t >> 5;
        float v = acc;
#pragma unroll
        for (int o = 1; o < 32; o <<= 1) {
            float n = __shfl_up_sync(0xffffffff, v, o);
            if (lane >= o) v += n;
        }
        if (lane == 31) swsum[wid] = v;
        __syncthreads();
        if (t == 0) {
            float r = 0.f;
#pragma unroll
            for (int w = 0; w < 8; w++) { swoff[w] = r; r += swsum[w]; }
        }
        __syncthreads();

        if (t < PRO_ACT) {
            float run = swoff[wid] + (v - acc);    // exclusive prefix
#pragma unroll 4
            for (int k = 0; k < PRO_RPT; k++) {
                run += smd[t * PRO_RPT + k];       // S1[r]-S2[r]
                d_w1bar[t * PRO_RPT + k] = 1.0f / (1.0f + __expf(run));
            }
        }
        __syncthreads();
        if (t == 0) {
            __threadfence();
            atomicExch(&d_flag, 1u);               // release
        }
    } else {
        // ---- wait for prologue ----
        if (t == 0) {
            while (atomicAdd(&d_flag, 0u) == 0u) __nanosleep(128);
            __threadfence();                       // acquire
        }
        __syncthreads();
    }

    // ---- output tile: out[i,j] = h[i] + g[i]*w1bar[j] ----
    const int j4 = blockIdx.x * TPB + t;
    if (j4 < N4) {
        const float4 w4 = reinterpret_cast<const float4*>(d_w1bar)[j4];
        const int i0 = blockIdx.y * ROWS_PER_BLK;
        float4* o4 = reinterpret_cast<float4*>(out);
#pragma unroll
        for (int k = 0; k < ROWS_PER_BLK; k++) {
            const int i = i0 + k;
            const float gv = d_g[i];
            const float hv = d_h[i];
            float4 o;
            o.x = fmaf(gv, w4.x, hv);
            o.y = fmaf(gv, w4.y, hv);
            o.z = fmaf(gv, w4.z, hv);
            o.w = fmaf(gv, w4.w, hv);
            __stcs(&o4[(size_t)i * N4 + j4], o);
        }
    }

    // ---- self-reset for graph replays ----
    if (t == 0) {
        const unsigned v = atomicAdd(&d_fin, 1u);
        if (v == TOTAL_BLOCKS - 1u) {
            atomicExch(&d_flag, 0u);
            atomicExch(&d_fin, 0u);
        }
    }
}

// ---------------------------------------------------------------------------
extern "C" void kernel_launch(void* const* d_in, const int* in_sizes, int n_in,
                              void* d_out, int out_size)
{
    const float* x   = (const float*)d_in[0];
    const float* a1  = (const float*)d_in[1];
    const float* c1  = (const float*)d_in[2];
    const float* a2  = (const float*)d_in[3];
    const float* c2  = (const float*)d_in[4];
    const float* wf1 = (const float*)d_in[5];
    const float* bf1 = (const float*)d_in[6];
    const float* wf2 = (const float*)d_in[7];
    const float* bf2 = (const float*)d_in[8];
    float* out = (float*)d_out;

    dim3 grid(GRID_X, GRID_Y);   // (8, 500) = 4000 blocks
    k_fused<<<grid, TPB>>>(x, a1, c1, a2, c2, wf1, bf1, wf2, bf2, out);
}

// round 5
// speedup vs baseline: 1.6341x; 1.4298x over previous
#include <cuda_runtime.h>

#define N_ROWS 8000
#define D 9
#define N4 2000            // N_ROWS / 4 (float4 columns)
#define OUT_TPB 256
#define ROWS_PER_BLK 16
#define CHUNK 64           // rows per K1 block
#define NB1 125            // K1 blocks: 125 * 64 = 8000
#define K1_TPB 256

// Scratch (device globals — zero-initialized, no allocation allowed)
__device__ float d_delta[N_ROWS];   // within-chunk inclusive cumsum of (s1-s2)
__device__ float d_csum[NB1];       // per-chunk totals
__device__ float d_g[N_ROWS];
__device__ float d_h[N_ROWS];
__device__ float d_w1bar[N_ROWS];
__device__ unsigned int d_tick;     // arrival ticket (self-resetting)

// ---------------------------------------------------------------------------
// K1: parallel rowstats across ~125 SMs + "last block finishes" scan.
//   delta[r] = sum_d [ ((x-c1)/a1)^2 - ((x-c2)/a2)^2 ]   (log-domain)
//   g[r] = f1[r]-f2[r],  h[r] = f2[r]
// Each block: local (64-row) inclusive cumsum via warp shuffles + chunk total.
// Last-arriving block: exclusive scan of 125 chunk totals, then
//   w1bar[r] = 1/(1+exp(prefix[r/64] + local[r]))  for all 8000 rows.
// ---------------------------------------------------------------------------
__global__ void __launch_bounds__(K1_TPB)
k_pro(const float* __restrict__ x,
      const float* __restrict__ a1, const float* __restrict__ c1,
      const float* __restrict__ a2, const float* __restrict__ c2,
      const float* __restrict__ wf1, const float* __restrict__ bf1,
      const float* __restrict__ wf2, const float* __restrict__ bf2)
{
    __shared__ float s_w0tot;        // warp-0 cumsum total (chunk combine)
    __shared__ float spref[128];     // chunk exclusive prefixes (last block)
    __shared__ float swt[4];
    __shared__ int   s_last;

    const int t = threadIdx.x;
    const int b = blockIdx.x;
    const unsigned lane = t & 31;
    const int w = t >> 5;

    // ---- rowstats: threads 0..63, one row each ----
    float delta = 0.0f;
    if (t < CHUNK) {
        const int r = b * CHUNK + t;
        const float inv1 = 1.0f / __ldg(a1);
        const float inv2 = 1.0f / __ldg(a2);
        const float k1 = -__ldg(c1) * inv1;
        const float k2 = -__ldg(c2) * inv2;
        float s1 = 0.f, s2 = 0.f;
        float f1 = __ldg(bf1), f2 = __ldg(bf2);
#pragma unroll
        for (int d = 0; d < D; d++) {
            float xv = __ldg(&x[r * D + d]);
            float u1 = fmaf(xv, inv1, k1);
            float u2 = fmaf(xv, inv2, k2);
            s1 = fmaf(u1, u1, s1);
            s2 = fmaf(u2, u2, s2);
            f1 = fmaf(xv, __ldg(&wf1[d]), f1);
            f2 = fmaf(xv, __ldg(&wf2[d]), f2);
        }
        delta = s1 - s2;
        d_g[r] = f1 - f2;
        d_h[r] = f2;
    }

    // ---- local inclusive cumsum over the 64 rows (2 warps) ----
    float v = delta;
#pragma unroll
    for (int o = 1; o < 32; o <<= 1) {
        float n = __shfl_up_sync(0xffffffff, v, o);
        if (lane >= o) v += n;
    }
    if (t == 31) s_w0tot = v;
    __syncthreads();
    if (w == 1 && t < CHUNK) v += s_w0tot;
    if (t < CHUNK) {
        d_delta[b * CHUNK + t] = v;
        if (t == CHUNK - 1) d_csum[b] = v;
    }
    __threadfence();                 // publish before arriving
    __syncthreads();

    if (t == 0) {
        unsigned tk = atomicAdd(&d_tick, 1u);
        s_last = (tk == NB1 - 1u);
    }
    __syncthreads();
    if (!s_last) return;

    // ---- last block: finish ----
    __threadfence();                 // acquire: see all blocks' writes

    // exclusive scan of 125 chunk totals (4 warps, shfl + combine)
    float orig = (t < NB1) ? d_csum[t] : 0.0f;
    float cv = orig;
#pragma unroll
    for (int o = 1; o < 32; o <<= 1) {
        float n = __shfl_up_sync(0xffffffff, cv, o);
        if (lane >= o) cv += n;
    }
    if (t < 128 && lane == 31) swt[w] = cv;
    __syncthreads();
    if (t < 128) {
        float off = 0.0f;
#pragma unroll
        for (int ww = 0; ww < 4; ww++) off += (ww < w) ? swt[ww] : 0.0f;
        spref[t] = off + cv - orig;  // exclusive prefix of chunk t
    }
    __syncthreads();

    // apply: w1bar[r] = sigmoid(prefix + local inclusive cumsum)   (L2-hot)
#pragma unroll 4
    for (int r = t; r < N_ROWS; r += K1_TPB) {
        float run = spref[r >> 6] + d_delta[r];   // S1[r]-S2[r]
        d_w1bar[r] = 1.0f / (1.0f + __expf(run));
    }

    if (t == 0) d_tick = 0;          // self-reset for graph replays
}

// ---------------------------------------------------------------------------
// K2: out[i,j] = h[i] + g[i]*w1bar[j]  — 256 MB of streaming stores (roofline)
// ---------------------------------------------------------------------------
__global__ void k_outer(float* __restrict__ out)
{
    int j4 = blockIdx.x * OUT_TPB + threadIdx.x;
    if (j4 >= N4) return;

    float4 w4 = reinterpret_cast<const float4*>(d_w1bar)[j4];
    int i0 = blockIdx.y * ROWS_PER_BLK;
    float4* o4 = reinterpret_cast<float4*>(out);

#pragma unroll
    for (int k = 0; k < ROWS_PER_BLK; k++) {
        int i = i0 + k;
        float gv = d_g[i];
        float hv = d_h[i];
        float4 o;
        o.x = fmaf(gv, w4.x, hv);
        o.y = fmaf(gv, w4.y, hv);
        o.z = fmaf(gv, w4.z, hv);
        o.w = fmaf(gv, w4.w, hv);
        __stcs(&o4[(size_t)i * N4 + j4], o);
    }
}

// ---------------------------------------------------------------------------
extern "C" void kernel_launch(void* const* d_in, const int* in_sizes, int n_in,
                              void* d_out, int out_size)
{
    const float* x   = (const float*)d_in[0];
    const float* a1  = (const float*)d_in[1];
    const float* c1  = (const float*)d_in[2];
    const float* a2  = (const float*)d_in[3];
    const float* c2  = (const float*)d_in[4];
    const float* wf1 = (const float*)d_in[5];
    const float* bf1 = (const float*)d_in[6];
    const float* wf2 = (const float*)d_in[7];
    const float* bf2 = (const float*)d_in[8];
    float* out = (float*)d_out;

    k_pro<<<NB1, K1_TPB>>>(x, a1, c1, a2, c2, wf1, bf1, wf2, bf2);

    dim3 grid((N4 + OUT_TPB - 1) / OUT_TPB, N_ROWS / ROWS_PER_BLK);  // (8, 500)
    k_outer<<<grid, OUT_TPB>>>(out);
}

// round 7
// speedup vs baseline: 1.9934x; 1.2199x over previous
#include <cuda_runtime.h>

#define N_ROWS 8000
#define D 9
#define N4 2000            // N_ROWS / 4 (float4 columns)
#define OUT_TPB 256
#define ROWS_PER_BLK 16
#define CHUNK 64           // rows per K1 block
#define NB1 125            // K1 blocks: 125 * 64 = 8000
#define K1_TPB 64

// Scratch (device globals — zero-initialized, no allocation allowed)
__device__ float d_delta[N_ROWS];   // within-chunk inclusive cumsum of (s1-s2)
__device__ float d_csum[NB1];       // per-chunk totals
__device__ float d_spref[NB1];      // exclusive prefix of chunk totals
__device__ float d_g[N_ROWS];
__device__ float d_h[N_ROWS];
__device__ unsigned int d_tick;     // arrival ticket (self-resetting)

// ---------------------------------------------------------------------------
// K1: parallel rowstats + local scans. NO serial 8000-row apply phase.
//   delta[r] = sum_d [ ((x-c1)/a1)^2 - ((x-c2)/a2)^2 ]   (log-domain)
//   d_delta  = within-chunk inclusive cumsum of delta
//   g[r] = f1[r]-f2[r],  h[r] = f2[r]
// Last-arriving block only scans the 125 chunk totals -> d_spref (tiny).
// ---------------------------------------------------------------------------
__global__ void __launch_bounds__(K1_TPB)
k_pro(const float* __restrict__ x,
      const float* __restrict__ a1, const float* __restrict__ c1,
      const float* __restrict__ a2, const float* __restrict__ c2,
      const float* __restrict__ wf1, const float* __restrict__ bf1,
      const float* __restrict__ wf2, const float* __restrict__ bf2)
{
    __shared__ float s_w0tot;
    __shared__ float swt[2];
    __shared__ int   s_last;

    const int t = threadIdx.x;
    const int b = blockIdx.x;
    const unsigned lane = t & 31;
    const int w = t >> 5;

    // ---- rowstats: one row per thread ----
    const int r = b * CHUNK + t;
    const float inv1 = 1.0f / __ldg(a1);
    const float inv2 = 1.0f / __ldg(a2);
    const float k1 = -__ldg(c1) * inv1;
    const float k2 = -__ldg(c2) * inv2;
    float s1 = 0.f, s2 = 0.f;
    float f1 = __ldg(bf1), f2 = __ldg(bf2);
#pragma unroll
    for (int d = 0; d < D; d++) {
        float xv = __ldg(&x[r * D + d]);
        float u1 = fmaf(xv, inv1, k1);
        float u2 = fmaf(xv, inv2, k2);
        s1 = fmaf(u1, u1, s1);
        s2 = fmaf(u2, u2, s2);
        f1 = fmaf(xv, __ldg(&wf1[d]), f1);
        f2 = fmaf(xv, __ldg(&wf2[d]), f2);
    }
    const float delta = s1 - s2;
    d_g[r] = f1 - f2;
    d_h[r] = f2;

    // ---- within-chunk inclusive cumsum (2 warps) ----
    float v = delta;
#pragma unroll
    for (int o = 1; o < 32; o <<= 1) {
        float n = __shfl_up_sync(0xffffffff, v, o);
        if (lane >= o) v += n;
    }
    if (t == 31) s_w0tot = v;
    __syncthreads();
    if (w == 1) v += s_w0tot;
    d_delta[r] = v;
    if (t == CHUNK - 1) d_csum[b] = v;

    __threadfence();                 // publish before arriving
    __syncthreads();
    if (t == 0) {
        unsigned tk = atomicAdd(&d_tick, 1u);
        s_last = (tk == NB1 - 1u);
    }
    __syncthreads();
    if (!s_last) return;

    // ---- last block: tiny scan of 125 chunk totals -> d_spref ----
    __threadfence();                 // acquire
    float orig = 0.0f;
    // thread t handles chunks t and t+64 (125 chunks, 64 threads)
    // simpler: warp 0 lane l scans serially in 4 steps via shfl over 125 vals
    // do it with 64 threads: two-level scan
    float c0 = (t < NB1) ? d_csum[t] : 0.0f;
    float c1v = (t + 64 < NB1) ? d_csum[t + 64] : 0.0f;
    // scan first 64 (2 warps)
    float a = c0;
#pragma unroll
    for (int o = 1; o < 32; o <<= 1) {
        float n = __shfl_up_sync(0xffffffff, a, o);
        if (lane >= o) a += n;
    }
    if (lane == 31) swt[w] = a;
    __syncthreads();
    float tot0 = swt[0];
    if (w == 1) a += tot0;
    float total64 = swt[0] + swt[1];        // sum of chunks 0..63? no:
    // swt[0]=sum chunks 0..31, swt[1]=sum chunks 32..63 (after warp scans)
    // a is inclusive over 0..t now.
    d_spref[t] = a - c0;                    // exclusive prefix for chunk t
    __syncthreads();
    // second group: chunks 64..124 (61 values)
    float bsc = c1v;
#pragma unroll
    for (int o = 1; o < 32; o <<= 1) {
        float n = __shfl_up_sync(0xffffffff, bsc, o);
        if (lane >= o) bsc += n;
    }
    if (lane == 31) swt[w] = bsc;           // warp-local totals of group 2
    __syncthreads();
    if (w == 1) bsc += swt[0];
    if (t + 64 < NB1)
        d_spref[t + 64] = total64 + bsc - c1v;  // exclusive prefix

    if (t == 0) d_tick = 0;          // self-reset for graph replays
    orig = orig;                     // silence unused warning path
}

// ---------------------------------------------------------------------------
// K2: out[i,j] = h[i] + g[i]*w1bar[j], with w1bar computed inline:
//   w1bar[j] = 1/(1+exp(spref[j>>6] + d_delta[j]))
// 4 columns per thread never straddle a 64-row chunk (4 | 64).
// 256 MB of streaming stores — the roofline.
// ---------------------------------------------------------------------------
__global__ void k_outer(float* __restrict__ out)
{
    int j4 = blockIdx.x * OUT_TPB + threadIdx.x;
    if (j4 >= N4) return;

    const float pre = __ldg(&d_spref[(j4 * 4) >> 6]);
    const float4 dl = reinterpret_cast<const float4*>(d_delta)[j4];
    float4 w4;
    w4.x = 1.0f / (1.0f + __expf(pre + dl.x));
    w4.y = 1.0f / (1.0f + __expf(pre + dl.y));
    w4.z = 1.0f / (1.0f + __expf(pre + dl.z));
    w4.w = 1.0f / (1.0f + __expf(pre + dl.w));

    int i0 = blockIdx.y * ROWS_PER_BLK;
    float4* o4 = reinterpret_cast<float4*>(out);

#pragma unroll
    for (int k = 0; k < ROWS_PER_BLK; k++) {
        int i = i0 + k;
        float gv = d_g[i];
        float hv = d_h[i];
        float4 o;
        o.x = fmaf(gv, w4.x, hv);
        o.y = fmaf(gv, w4.y, hv);
        o.z = fmaf(gv, w4.z, hv);
        o.w = fmaf(gv, w4.w, hv);
        __stcs(&o4[(size_t)i * N4 + j4], o);
    }
}

// ---------------------------------------------------------------------------
extern "C" void kernel_launch(void* const* d_in, const int* in_sizes, int n_in,
                              void* d_out, int out_size)
{
    const float* x   = (const float*)d_in[0];
    const float* a1  = (const float*)d_in[1];
    const float* c1  = (const float*)d_in[2];
    const float* a2  = (const float*)d_in[3];
    const float* c2  = (const float*)d_in[4];
    const float* wf1 = (const float*)d_in[5];
    const float* bf1 = (const float*)d_in[6];
    const float* wf2 = (const float*)d_in[7];
    const float* bf2 = (const float*)d_in[8];
    float* out = (float*)d_out;

    k_pro<<<NB1, K1_TPB>>>(x, a1, c1, a2, c2, wf1, bf1, wf2, bf2);

    dim3 grid((N4 + OUT_TPB - 1) / OUT_TPB, N_ROWS / ROWS_PER_BLK);  // (8, 500)
    k_outer<<<grid, OUT_TPB>>>(out);
}